// round 1
// baseline (speedup 1.0000x reference)
#include <cuda_runtime.h>

#define B_   32
#define S_   512
#define E_   8
#define H_   768
#define KG_  100
#define MH_  1000
#define NROW (B_*E_)   /* 256 */

// Scratch (device globals — no allocation allowed)
__device__ float g_Hs[NROW * MH_];                     // 256x1000 post-relu hidden
__device__ __align__(16) float g_ENT[3][NROW * H_];    // 3 K-split partials of ent

// ---------------------------------------------------------------------------
// K1: Hs = relu(X @ W1 + b1)   X:[256,100]  W1:[100,1000]
// grid (4, 32): x = column group of 256, y = row tile of 8. block 256.
// ---------------------------------------------------------------------------
__global__ void k1_mlp1(const float* __restrict__ X,
                        const float* __restrict__ W1,
                        const float* __restrict__ b1) {
    __shared__ float xs[8][KG_];
    const int rb = blockIdx.y * 8;
    const int j  = blockIdx.x * 256 + threadIdx.x;

    for (int idx = threadIdx.x; idx < 8 * KG_; idx += 256) {
        int r = idx / KG_, k = idx - r * KG_;
        xs[r][k] = X[(rb + r) * KG_ + k];
    }
    __syncthreads();

    if (j < MH_) {
        const float bj = b1[j];
        float acc[8];
        #pragma unroll
        for (int r = 0; r < 8; r++) acc[r] = bj;

        #pragma unroll 4
        for (int k = 0; k < KG_; k++) {
            float w = W1[k * MH_ + j];
            #pragma unroll
            for (int r = 0; r < 8; r++) acc[r] = fmaf(xs[r][k], w, acc[r]);
        }
        #pragma unroll
        for (int r = 0; r < 8; r++)
            g_Hs[(rb + r) * MH_ + j] = fmaxf(acc[r], 0.0f);
    }
}

// ---------------------------------------------------------------------------
// K2: ENT_part[kz] = Hs[:, kchunk] @ W2[kchunk, :]  (+ b2 folded into kz==0)
// M=256, N=768, K=1000. grid (6, 8, 3): x = 128-col tile, y = 32-row tile,
// z = K split. block 256: tx=tid&31 -> 4 cols (float4), ty=tid>>5 -> 4 rows.
// ---------------------------------------------------------------------------
__global__ void k2_mlp2(const float* __restrict__ W2,
                        const float* __restrict__ b2) {
    __shared__ float hs[32][336];
    const int cb = blockIdx.x * 128;
    const int rb = blockIdx.y * 32;
    const int kz = blockIdx.z;
    const int kb = kz * 334;
    const int kc = min(334, MH_ - kb);
    const int tid = threadIdx.x;

    // Stage the 32 x kc slice of Hs into smem (coalesced along k).
    for (int idx = tid; idx < 32 * kc; idx += 256) {
        int r = idx / kc, k = idx - r * kc;
        hs[r][k] = g_Hs[(rb + r) * MH_ + kb + k];
    }
    __syncthreads();

    const int tx = tid & 31;
    const int ty = tid >> 5;
    const int col = cb + tx * 4;

    float acc[4][4];
    if (kz == 0) {
        float4 bv = *(const float4*)(b2 + col);
        #pragma unroll
        for (int i = 0; i < 4; i++) {
            acc[i][0] = bv.x; acc[i][1] = bv.y; acc[i][2] = bv.z; acc[i][3] = bv.w;
        }
    } else {
        #pragma unroll
        for (int i = 0; i < 4; i++)
            #pragma unroll
            for (int j = 0; j < 4; j++) acc[i][j] = 0.0f;
    }

    const float4* __restrict__ W24 = (const float4*)W2;
    const int r0 = ty * 4;

    #pragma unroll 2
    for (int k = 0; k < kc; k++) {
        float4 w = W24[((kb + k) * H_ + col) >> 2];
        float h0 = hs[r0 + 0][k];
        float h1 = hs[r0 + 1][k];
        float h2 = hs[r0 + 2][k];
        float h3 = hs[r0 + 3][k];
        acc[0][0] = fmaf(h0, w.x, acc[0][0]); acc[0][1] = fmaf(h0, w.y, acc[0][1]);
        acc[0][2] = fmaf(h0, w.z, acc[0][2]); acc[0][3] = fmaf(h0, w.w, acc[0][3]);
        acc[1][0] = fmaf(h1, w.x, acc[1][0]); acc[1][1] = fmaf(h1, w.y, acc[1][1]);
        acc[1][2] = fmaf(h1, w.z, acc[1][2]); acc[1][3] = fmaf(h1, w.w, acc[1][3]);
        acc[2][0] = fmaf(h2, w.x, acc[2][0]); acc[2][1] = fmaf(h2, w.y, acc[2][1]);
        acc[2][2] = fmaf(h2, w.z, acc[2][2]); acc[2][3] = fmaf(h2, w.w, acc[2][3]);
        acc[3][0] = fmaf(h3, w.x, acc[3][0]); acc[3][1] = fmaf(h3, w.y, acc[3][1]);
        acc[3][2] = fmaf(h3, w.z, acc[3][2]); acc[3][3] = fmaf(h3, w.w, acc[3][3]);
    }

    #pragma unroll
    for (int i = 0; i < 4; i++) {
        int r = rb + r0 + i;
        float4 o = make_float4(acc[i][0], acc[i][1], acc[i][2], acc[i][3]);
        *(float4*)(&g_ENT[kz][r * H_ + col]) = o;
    }
}

// ---------------------------------------------------------------------------
// K3: out[b,s,:] = word_embedding[ids[b,s]] + sum_e mask[b,e,s] * ent[b*E+e,:]
// grid 16384 (one (b,s) row per block), block 192 (768 floats = 192 x float4).
// ---------------------------------------------------------------------------
__global__ void k3_fuse(const int*   __restrict__ ids,
                        const float* __restrict__ mask,
                        const float* __restrict__ we,
                        float*       __restrict__ out) {
    const int row = blockIdx.x;
    const int b = row >> 9;
    const int s = row & (S_ - 1);
    const int tid = threadIdx.x;

    __shared__ float sm[E_];
    __shared__ int   swid;

    if (tid < E_)  sm[tid] = mask[(b * E_ + tid) * S_ + s];
    if (tid == E_) swid = ids[row];
    __syncthreads();

    const int wid = swid;
    float4 v = ((const float4*)we)[(long long)wid * (H_ / 4) + tid];

    #pragma unroll
    for (int e = 0; e < E_; e++) {
        float m = sm[e];
        if (m != 0.0f) {
            int r = b * E_ + e;
            int idx = r * (H_ / 4) + tid;
            float4 p0 = ((const float4*)g_ENT[0])[idx];
            float4 p1 = ((const float4*)g_ENT[1])[idx];
            float4 p2 = ((const float4*)g_ENT[2])[idx];
            v.x = fmaf(m, p0.x + p1.x + p2.x, v.x);
            v.y = fmaf(m, p0.y + p1.y + p2.y, v.y);
            v.z = fmaf(m, p0.z + p1.z + p2.z, v.z);
            v.w = fmaf(m, p0.w + p1.w + p2.w, v.w);
        }
    }

    ((float4*)out)[(long long)row * (H_ / 4) + tid] = v;
}

// ---------------------------------------------------------------------------
extern "C" void kernel_launch(void* const* d_in, const int* in_sizes, int n_in,
                              void* d_out, int out_size) {
    const int*   ids  = (const int*)  d_in[0];   // input_ids        [32,512]
    const float* X    = (const float*)d_in[1];   // entity_embeddings[32,8,100]
    const float* msk  = (const float*)d_in[2];   // entity_mask      [32,8,512]
    const float* we   = (const float*)d_in[3];   // word_embedding   [30522,768]
    const float* W1   = (const float*)d_in[4];   // [100,1000]
    const float* b1   = (const float*)d_in[5];   // [1000]
    const float* W2   = (const float*)d_in[6];   // [1000,768]
    const float* b2   = (const float*)d_in[7];   // [768]
    float* out = (float*)d_out;                  // [32,512,768]

    k1_mlp1<<<dim3(4, 32), 256>>>(X, W1, b1);
    k2_mlp2<<<dim3(6, 8, 3), 256>>>(W2, b2);
    k3_fuse<<<B_ * S_, H_ / 4>>>(ids, msk, we, out);
}

// round 2
// speedup vs baseline: 1.8551x; 1.8551x over previous
#include <cuda_runtime.h>

#define B_   32
#define S_   512
#define E_   8
#define H_   768
#define KG_  100
#define MH_  1000
#define NROW (B_*E_)     /* 256 */
#define KSPLIT 6
#define KC   167         /* ceil(1000/6), zero-padded */

typedef unsigned long long u64;

// Scratch (device globals — no allocation allowed)
__device__ float g_Hs[NROW * MH_];                       // 256x1000 post-relu hidden
__device__ __align__(16) float g_ENT[KSPLIT][NROW * H_]; // K-split partials of ent

// ---- packed fp32x2 helpers (sm_100+ PTX) ----------------------------------
__device__ __forceinline__ u64 pk2(float a, float b) {
    u64 r; asm("mov.b64 %0, {%1,%2};" : "=l"(r) : "f"(a), "f"(b)); return r;
}
__device__ __forceinline__ u64 fma2(u64 a, u64 b, u64 c) {
    u64 d; asm("fma.rn.f32x2 %0, %1, %2, %3;" : "=l"(d) : "l"(a), "l"(b), "l"(c)); return d;
}
__device__ __forceinline__ float2 up2(u64 v) {
    float2 f; asm("mov.b64 {%0,%1}, %2;" : "=f"(f.x), "=f"(f.y) : "l"(v)); return f;
}

// ---------------------------------------------------------------------------
// K1: Hs = relu(X @ W1 + b1)   X:[256,100]  W1:[100,1000]
// grid (4, 64): x = 256-col group, y = 4-row tile. block 256.
// Rows packed in pairs -> 2 FFMA2 per k per thread.
// ---------------------------------------------------------------------------
__global__ void __launch_bounds__(256) k1_mlp1(const float* __restrict__ X,
                                               const float* __restrict__ W1,
                                               const float* __restrict__ b1) {
    __shared__ u64 xp[2][KG_];   // row pairs (r0,r1),(r2,r3) duplicated per k
    const int rb = blockIdx.y * 4;
    const int j  = blockIdx.x * 256 + threadIdx.x;

    for (int idx = threadIdx.x; idx < 2 * KG_; idx += 256) {
        int p = idx / KG_, k = idx - p * KG_;
        xp[p][k] = pk2(X[(rb + 2*p) * KG_ + k], X[(rb + 2*p + 1) * KG_ + k]);
    }
    __syncthreads();

    if (j < MH_) {
        const float bj = b1[j];
        u64 acc0 = pk2(bj, bj);
        u64 acc1 = acc0;

        #pragma unroll 10
        for (int k = 0; k < KG_; k++) {
            float w = W1[k * MH_ + j];
            u64 wp = pk2(w, w);
            acc0 = fma2(xp[0][k], wp, acc0);
            acc1 = fma2(xp[1][k], wp, acc1);
        }
        float2 a0 = up2(acc0), a1 = up2(acc1);
        g_Hs[(rb + 0) * MH_ + j] = fmaxf(a0.x, 0.0f);
        g_Hs[(rb + 1) * MH_ + j] = fmaxf(a0.y, 0.0f);
        g_Hs[(rb + 2) * MH_ + j] = fmaxf(a1.x, 0.0f);
        g_Hs[(rb + 3) * MH_ + j] = fmaxf(a1.y, 0.0f);
    }
}

// ---------------------------------------------------------------------------
// K2: ENT_part[kz] = Hs[:, kchunk] @ W2[kchunk, :]  (+ b2 folded into kz==0)
// M=256, N=768, K=1000. grid (3, 8, 6): x = 256-col tile, y = 32-row tile,
// z = K-split (167 each, zero padded). block 256: tx -> 8 cols, ty -> 4 rows.
// h values live in smem as DUPLICATED f32x2 pairs -> LDS.128 feeds FFMA2
// directly, no per-iteration h packing.
// ---------------------------------------------------------------------------
__global__ void __launch_bounds__(256, 1) k2_mlp2(const float* __restrict__ W2,
                                                  const float* __restrict__ b2) {
    // hd[k][r] = {h, h} for row r at depth k. Pad row dim to 34 u64 so
    // consecutive-k writes land 16 mod 128 bytes apart (4 banks) and
    // (k*34 + r0) stays 16B-aligned for LDS.128 (r0 multiple of 4).
    __shared__ u64 hd[KC][34];

    const int cb = blockIdx.x * 256;
    const int rb = blockIdx.y * 32;
    const int kz = blockIdx.z;
    const int kb = kz * KC;
    const int tid = threadIdx.x;

    // Stage 32 x 167 slice (coalesced along k), duplicate into pairs.
    for (int idx = tid; idx < 32 * KC; idx += 256) {
        int r = idx / KC, k = idx - r * KC;
        int kk = kb + k;
        float h = (kk < MH_) ? g_Hs[(rb + r) * MH_ + kk] : 0.0f;
        hd[k][r] = pk2(h, h);
    }
    __syncthreads();

    const int tx = tid & 31;
    const int ty = tid >> 5;
    const int r0 = ty * 4;
    const int col = cb + tx * 8;

    u64 acc[4][4];   // [row][col-pair]
    if (kz == 0) {
        float4 bv0 = *(const float4*)(b2 + col);
        float4 bv1 = *(const float4*)(b2 + col + 4);
        u64 p0 = pk2(bv0.x, bv0.y), p1 = pk2(bv0.z, bv0.w);
        u64 p2 = pk2(bv1.x, bv1.y), p3 = pk2(bv1.z, bv1.w);
        #pragma unroll
        for (int i = 0; i < 4; i++) { acc[i][0]=p0; acc[i][1]=p1; acc[i][2]=p2; acc[i][3]=p3; }
    } else {
        #pragma unroll
        for (int i = 0; i < 4; i++)
            #pragma unroll
            for (int jj = 0; jj < 4; jj++) acc[i][jj] = 0ULL;
    }

    const float4* __restrict__ W24 = (const float4*)W2;

    #pragma unroll 4
    for (int k = 0; k < KC; k++) {
        // 4 duplicated h pairs for this thread's rows (2 x LDS.128)
        u64 h01_0 = hd[k][r0 + 0];
        u64 h01_1 = hd[k][r0 + 1];
        u64 h23_0 = hd[k][r0 + 2];
        u64 h23_1 = hd[k][r0 + 3];

        long long wbase = ((long long)(kb + k) * H_ + col) >> 2;
        float4 w0 = W24[wbase];
        float4 w1 = W24[wbase + 1];
        u64 wp0 = pk2(w0.x, w0.y), wp1 = pk2(w0.z, w0.w);
        u64 wp2 = pk2(w1.x, w1.y), wp3 = pk2(w1.z, w1.w);

        acc[0][0] = fma2(h01_0, wp0, acc[0][0]);
        acc[0][1] = fma2(h01_0, wp1, acc[0][1]);
        acc[0][2] = fma2(h01_0, wp2, acc[0][2]);
        acc[0][3] = fma2(h01_0, wp3, acc[0][3]);
        acc[1][0] = fma2(h01_1, wp0, acc[1][0]);
        acc[1][1] = fma2(h01_1, wp1, acc[1][1]);
        acc[1][2] = fma2(h01_1, wp2, acc[1][2]);
        acc[1][3] = fma2(h01_1, wp3, acc[1][3]);
        acc[2][0] = fma2(h23_0, wp0, acc[2][0]);
        acc[2][1] = fma2(h23_0, wp1, acc[2][1]);
        acc[2][2] = fma2(h23_0, wp2, acc[2][2]);
        acc[2][3] = fma2(h23_0, wp3, acc[2][3]);
        acc[3][0] = fma2(h23_1, wp0, acc[3][0]);
        acc[3][1] = fma2(h23_1, wp1, acc[3][1]);
        acc[3][2] = fma2(h23_1, wp2, acc[3][2]);
        acc[3][3] = fma2(h23_1, wp3, acc[3][3]);
    }

    float* dst = g_ENT[kz];
    #pragma unroll
    for (int i = 0; i < 4; i++) {
        int r = rb + r0 + i;
        float2 a0 = up2(acc[i][0]), a1 = up2(acc[i][1]);
        float2 a2 = up2(acc[i][2]), a3 = up2(acc[i][3]);
        *(float4*)(dst + r * H_ + col)     = make_float4(a0.x, a0.y, a1.x, a1.y);
        *(float4*)(dst + r * H_ + col + 4) = make_float4(a2.x, a2.y, a3.x, a3.y);
    }
}

// ---------------------------------------------------------------------------
// kR: reduce the 6 K-split partials in place into g_ENT[0].
// 49152 float4 total; grid 96 x block 256, 2 float4 per thread.
// ---------------------------------------------------------------------------
__global__ void __launch_bounds__(256) kR_reduce() {
    int i = blockIdx.x * 512 + threadIdx.x;
    #pragma unroll
    for (int t = 0; t < 2; t++, i += 256) {
        float4 a = ((const float4*)g_ENT[0])[i];
        #pragma unroll
        for (int p = 1; p < KSPLIT; p++) {
            float4 b = ((const float4*)g_ENT[p])[i];
            a.x += b.x; a.y += b.y; a.z += b.z; a.w += b.w;
        }
        ((float4*)g_ENT[0])[i] = a;
    }
}

// ---------------------------------------------------------------------------
// K3: out[b,s,:] = word_embedding[ids[b,s]] + sum_e mask[b,e,s] * ent[b*E+e,:]
// grid 16384 (one (b,s) row per block), block 192 (768 floats = 192 float4).
// No smem / no syncthreads: all per-row scalars come in as broadcast loads.
// ---------------------------------------------------------------------------
__global__ void __launch_bounds__(192) k3_fuse(const int*   __restrict__ ids,
                                               const float* __restrict__ mask,
                                               const float* __restrict__ we,
                                               float*       __restrict__ out) {
    const int row = blockIdx.x;
    const int b = row >> 9;
    const int s = row & (S_ - 1);
    const int tid = threadIdx.x;

    const int wid = __ldg(ids + row);                 // broadcast

    float m[E_];
    #pragma unroll
    for (int e = 0; e < E_; e++)
        m[e] = __ldg(mask + (b * E_ + e) * S_ + s);   // broadcast, independent

    float4 v = ((const float4*)we)[(long long)wid * (H_ / 4) + tid];

    #pragma unroll
    for (int e = 0; e < E_; e++) {
        if (m[e] != 0.0f) {
            float4 p = ((const float4*)g_ENT[0])[(b * E_ + e) * (H_ / 4) + tid];
            v.x = fmaf(m[e], p.x, v.x);
            v.y = fmaf(m[e], p.y, v.y);
            v.z = fmaf(m[e], p.z, v.z);
            v.w = fmaf(m[e], p.w, v.w);
        }
    }

    ((float4*)out)[(long long)row * (H_ / 4) + tid] = v;
}

// ---------------------------------------------------------------------------
extern "C" void kernel_launch(void* const* d_in, const int* in_sizes, int n_in,
                              void* d_out, int out_size) {
    const int*   ids  = (const int*)  d_in[0];   // input_ids        [32,512]
    const float* X    = (const float*)d_in[1];   // entity_embeddings[32,8,100]
    const float* msk  = (const float*)d_in[2];   // entity_mask      [32,8,512]
    const float* we   = (const float*)d_in[3];   // word_embedding   [30522,768]
    const float* W1   = (const float*)d_in[4];   // [100,1000]
    const float* b1   = (const float*)d_in[5];   // [1000]
    const float* W2   = (const float*)d_in[6];   // [1000,768]
    const float* b2   = (const float*)d_in[7];   // [768]
    float* out = (float*)d_out;                  // [32,512,768]

    k1_mlp1<<<dim3(4, 64), 256>>>(X, W1, b1);
    k2_mlp2<<<dim3(3, 8, KSPLIT), 256>>>(W2, b2);
    kR_reduce<<<96, 256>>>();
    k3_fuse<<<B_ * S_, 192>>>(ids, msk, we, out);
}